// round 1
// baseline (speedup 1.0000x reference)
#include <cuda_runtime.h>
#include <cuda_bf16.h>

// PositionalEmbedding: out[b, flat] = x[b, flat] + pe_flat[flat],
// where pe is computed in [h, w, ch] order and raw-reshaped to [ch, h, w].
// B=32, C=256, H=64, W=64. Pure HBM-bound elementwise add with cheap
// on-the-fly pe computation (2 FMAs/elt) using per-channel fused coeffs.

#define B_DIM 32
#define C_DIM 256
#define H_DIM 64
#define W_DIM 64

// total elements = 32*256*64*64 = 33,554,432 (fits in int)
#define N_TOTAL (B_DIM * C_DIM * H_DIM * W_DIM)
#define M_BATCH (C_DIM * H_DIM * W_DIM)   // 1,048,576 = 2^20

__global__ __launch_bounds__(256)
void pe_add_kernel(const float* __restrict__ x,
                   const float* __restrict__ Wt,
                   const float* __restrict__ bias,
                   float* __restrict__ out)
{
    __shared__ float sA[C_DIM];
    __shared__ float sB[C_DIM];
    __shared__ float sC[C_DIM];

    const int tid = threadIdx.x;
    // blockDim == 256 == C_DIM: each thread preps one channel's coefficients.
    {
        const float w0 = Wt[tid * 4 + 0];
        const float w1 = Wt[tid * 4 + 1];
        const float w2 = Wt[tid * 4 + 2];
        const float w3 = Wt[tid * 4 + 3];
        sA[tid] = w0 - w2;            // multiplies u = j/63
        sB[tid] = w1 - w3;            // multiplies v = i/63
        sC[tid] = w2 + w3 + bias[tid];
    }
    __syncthreads();

    const float inv63 = 1.0f / 63.0f;
    const int n4 = N_TOTAL / 4;       // 8,388,608 float4s
    const int stride = gridDim.x * blockDim.x;

    for (int q = blockIdx.x * blockDim.x + tid; q < n4; q += stride) {
        const int t  = q << 2;                 // element index, multiple of 4
        const int tm = t & (M_BATCH - 1);      // index within one batch image
        const int i  = tm >> 14;               // row    (tm / (64*256))
        const int j  = (tm >> 8) & 63;         // col    ((tm / 256) % 64)
        const int c  = t & 255;                // channel base (multiple of 4)

        const float u = (float)j * inv63;
        const float v = (float)i * inv63;

        // Aligned 16B shared loads: c % 4 == 0 always.
        const float4 a4 = *reinterpret_cast<const float4*>(sA + c);
        const float4 b4 = *reinterpret_cast<const float4*>(sB + c);
        const float4 c4 = *reinterpret_cast<const float4*>(sC + c);

        const float4 xv = reinterpret_cast<const float4*>(x)[q];

        float4 o;
        o.x = xv.x + fmaf(a4.x, u, fmaf(b4.x, v, c4.x));
        o.y = xv.y + fmaf(a4.y, u, fmaf(b4.y, v, c4.y));
        o.z = xv.z + fmaf(a4.z, u, fmaf(b4.z, v, c4.z));
        o.w = xv.w + fmaf(a4.w, u, fmaf(b4.w, v, c4.w));

        reinterpret_cast<float4*>(out)[q] = o;
    }
}

extern "C" void kernel_launch(void* const* d_in, const int* in_sizes, int n_in,
                              void* d_out, int out_size)
{
    const float* x  = (const float*)d_in[0];   // [32,256,64,64]
    const float* Wt = (const float*)d_in[1];   // [256,4]
    const float* b  = (const float*)d_in[2];   // [256]
    float* out = (float*)d_out;

    (void)in_sizes; (void)n_in; (void)out_size;

    const int threads = 256;
    // 8.4M float4s; ~8 iters/thread at 4096 blocks. Memory-bound streaming.
    const int blocks = 4096;
    pe_add_kernel<<<blocks, threads>>>(x, Wt, b, out);
}